// round 1
// baseline (speedup 1.0000x reference)
#include <cuda_runtime.h>
#include <math.h>

// Problem constants
#define B_  64
#define T_  25
#define BT  1600        // B*T
#define E_  100
#define U_  1000
#define V_  32001
#define G3  3000        // 3*U

typedef unsigned long long ull;

// ---------------- scratch (device globals; no allocation allowed) ----------
__device__ float g_M[U_ * E_];      // fc_w @ emb_table   [1000,100]
__device__ float g_c[128];          // fc_b @ emb_table   [100]
__device__ float g_embd[BT * E_];   // gathered decoder-input embeddings
__device__ int   g_tok[BT];         // tokens (for mask)
__device__ float g_gx[BT * G3];     // emb_d @ dec_kernel + dec_bias[0]
__device__ float g_h1[BT * U_];     // GRU output (masked)

// ---------------- packed f32x2 helpers (Blackwell dual-fp32 path) ----------
__device__ __forceinline__ ull f2pack(float lo, float hi) {
    ull r; asm("mov.b64 %0, {%1, %2};" : "=l"(r) : "f"(lo), "f"(hi)); return r;
}
__device__ __forceinline__ void f2unpack(ull v, float& lo, float& hi) {
    asm("mov.b64 {%0, %1}, %2;" : "=f"(lo), "=f"(hi) : "l"(v));
}
__device__ __forceinline__ ull ffma2(ull a, ull b, ull c) {
    ull d; asm("fma.rn.f32x2 %0, %1, %2, %3;" : "=l"(d) : "l"(a), "l"(b), "l"(c)); return d;
}

// ---------------- kernel: zero M and c --------------------------------------
__global__ void k_zero() {
    int i = blockIdx.x * 256 + threadIdx.x;
    if (i < U_ * E_)              g_M[i] = 0.f;
    else if (i < U_ * E_ + 128)   g_c[i - U_ * E_] = 0.f;
}

// ---------------- kernel: c = fc_b @ emb_table ------------------------------
__global__ __launch_bounds__(128) void k_c(const float* __restrict__ fcb,
                                           const float* __restrict__ emb) {
    __shared__ float s[4][100];
    const int w = threadIdx.x >> 5, l = threadIdx.x & 31;
    const int chunk = 501;                       // ceil(32001/64)
    const int v0 = blockIdx.x * chunk;
    const int v1 = min(v0 + chunk, V_);
    float a0 = 0.f, a1 = 0.f, a2 = 0.f, a3 = 0.f;
    if (l < 25) {
        for (int v = v0 + w; v < v1; v += 4) {
            float fb = fcb[v];
            float4 e4 = *(const float4*)(emb + (size_t)v * E_ + l * 4);
            a0 = fmaf(fb, e4.x, a0); a1 = fmaf(fb, e4.y, a1);
            a2 = fmaf(fb, e4.z, a2); a3 = fmaf(fb, e4.w, a3);
        }
        s[w][l * 4 + 0] = a0; s[w][l * 4 + 1] = a1;
        s[w][l * 4 + 2] = a2; s[w][l * 4 + 3] = a3;
    }
    __syncthreads();
    int t = threadIdx.x;
    if (t < 100) {
        float sum = s[0][t] + s[1][t] + s[2][t] + s[3][t];
        atomicAdd(&g_c[t], sum);
    }
}

// ---------------- kernel: gather decoder input embeddings -------------------
__global__ __launch_bounds__(128) void k_gather(const int* __restrict__ target,
                                                const int* __restrict__ start_tok,
                                                const float* __restrict__ emb) {
    const int bt = blockIdx.x;
    const int b = bt / T_, t = bt % T_;
    const int tok = (t == 0) ? start_tok[0] : target[b * T_ + t - 1];
    if (threadIdx.x == 0) g_tok[bt] = tok;
    for (int e = threadIdx.x; e < E_; e += blockDim.x)
        g_embd[bt * E_ + e] = emb[(size_t)tok * E_ + e];
}

// ---------------- kernel: M += fc_w @ emb (split-K, atomics) ----------------
// BM=64 (u), BN=128 (e pad; 100 valid), BK=32 (v), 256 threads, 8x4 per thread
__global__ __launch_bounds__(256) void k_gemm_M(const float* __restrict__ fcw,
                                                const float* __restrict__ emb) {
    __shared__ __align__(16) float As[32][72];
    __shared__ __align__(16) float Bs[32][128];
    const int t = threadIdx.x;
    const int tx = t & 31, ty = t >> 5;
    const int u0 = blockIdx.x * 64;
    const int KS = 1001;                          // ceil(32001/32 splits)
    const int vbeg = blockIdx.y * KS;
    const int vend = min(vbeg + KS, V_);

    ull acc[8][2];
#pragma unroll
    for (int i = 0; i < 8; i++) { acc[i][0] = 0ull; acc[i][1] = 0ull; }

    for (int k0 = vbeg; k0 < vend; k0 += 32) {
#pragma unroll
        for (int r = 0; r < 8; r++) {
            int m = ty * 8 + r;
            int u = u0 + m;
            int v = k0 + tx;
            As[tx][m] = (u < U_ && v < vend) ? fcw[(size_t)u * V_ + v] : 0.f;
        }
#pragma unroll
        for (int i = 0; i < 16; i++) {
            int idx = t + i * 256;
            int kk = idx >> 7, e = idx & 127;
            int v = k0 + kk;
            Bs[kk][e] = (e < E_ && v < vend) ? emb[(size_t)v * E_ + e] : 0.f;
        }
        __syncthreads();
#pragma unroll
        for (int kk = 0; kk < 32; kk++) {
            float4 b4 = *(const float4*)&Bs[kk][tx * 4];
            ull b01 = f2pack(b4.x, b4.y);
            ull b23 = f2pack(b4.z, b4.w);
            float4 av0 = *(const float4*)&As[kk][ty * 8];
            float4 av1 = *(const float4*)&As[kk][ty * 8 + 4];
            float av[8] = {av0.x, av0.y, av0.z, av0.w, av1.x, av1.y, av1.z, av1.w};
#pragma unroll
            for (int i = 0; i < 8; i++) {
                ull aa = f2pack(av[i], av[i]);
                acc[i][0] = ffma2(aa, b01, acc[i][0]);
                acc[i][1] = ffma2(aa, b23, acc[i][1]);
            }
        }
        __syncthreads();
    }

    if (tx < 25) {
#pragma unroll
        for (int i = 0; i < 8; i++) {
            int u = u0 + ty * 8 + i;
            if (u < U_) {
                float e0, e1, e2, e3;
                f2unpack(acc[i][0], e0, e1);
                f2unpack(acc[i][1], e2, e3);
                float* p = &g_M[u * E_ + tx * 4];
                atomicAdd(p + 0, e0); atomicAdd(p + 1, e1);
                atomicAdd(p + 2, e2); atomicAdd(p + 3, e3);
            }
        }
    }
}

// ---------------- kernel: gx = emb_d @ dec_kernel + dec_bias[0] -------------
// BM=64 (bt), BN=128 (j), BK=25, K=100
__global__ __launch_bounds__(256) void k_gemm_gx(const float* __restrict__ W,
                                                 const float* __restrict__ bias) {
    __shared__ __align__(16) float As[25][72];
    __shared__ __align__(16) float Bs[25][128];
    const int t = threadIdx.x;
    const int tx = t & 31, ty = t >> 5;
    const int j0 = blockIdx.x * 128;
    const int m0 = blockIdx.y * 64;

    ull acc[8][2];
#pragma unroll
    for (int i = 0; i < 8; i++) { acc[i][0] = 0ull; acc[i][1] = 0ull; }

    for (int k0 = 0; k0 < E_; k0 += 25) {
        for (int idx = t; idx < 64 * 25; idx += 256) {
            int m = idx / 25, k = idx % 25;
            As[k][m] = g_embd[(m0 + m) * E_ + k0 + k];
        }
        for (int idx = t; idx < 25 * 128; idx += 256) {
            int k = idx >> 7, j = idx & 127;
            int jj = j0 + j;
            Bs[k][j] = (jj < G3) ? W[(size_t)(k0 + k) * G3 + jj] : 0.f;
        }
        __syncthreads();
#pragma unroll
        for (int kk = 0; kk < 25; kk++) {
            float4 b4 = *(const float4*)&Bs[kk][tx * 4];
            ull b01 = f2pack(b4.x, b4.y);
            ull b23 = f2pack(b4.z, b4.w);
            float4 av0 = *(const float4*)&As[kk][ty * 8];
            float4 av1 = *(const float4*)&As[kk][ty * 8 + 4];
            float av[8] = {av0.x, av0.y, av0.z, av0.w, av1.x, av1.y, av1.z, av1.w};
#pragma unroll
            for (int i = 0; i < 8; i++) {
                ull aa = f2pack(av[i], av[i]);
                acc[i][0] = ffma2(aa, b01, acc[i][0]);
                acc[i][1] = ffma2(aa, b23, acc[i][1]);
            }
        }
        __syncthreads();
    }

    const int j = j0 + tx * 4;
#pragma unroll
    for (int i = 0; i < 8; i++) {
        int m = m0 + ty * 8 + i;           // < 1600 always (25*64 exact)
        float e0, e1, e2, e3;
        f2unpack(acc[i][0], e0, e1);
        f2unpack(acc[i][1], e2, e3);
        float* p = &g_gx[(size_t)m * G3 + j];
        if (j + 0 < G3) p[0] = e0 + bias[j + 0];
        if (j + 1 < G3) p[1] = e1 + bias[j + 1];
        if (j + 2 < G3) p[2] = e2 + bias[j + 2];
        if (j + 3 < G3) p[3] = e3 + bias[j + 3];
    }
}

// ---------------- kernel: GRU nonlinearity + mask ---------------------------
__global__ void k_h1(const float* __restrict__ dec_bias) {
    int idx = blockIdx.x * 256 + threadIdx.x;
    if (idx >= BT * U_) return;
    int bt = idx / U_, u = idx - bt * U_;
    float h;
    if (g_tok[bt] == 0) {
        h = 0.f;
    } else {
        float xz = g_gx[(size_t)bt * G3 + u];
        float xr = g_gx[(size_t)bt * G3 + 1000 + u];
        float xh = g_gx[(size_t)bt * G3 + 2000 + u];
        float bz = dec_bias[3000 + u];
        float br = dec_bias[4000 + u];
        float bh = dec_bias[5000 + u];
        float z = 1.f / (1.f + expf(-(xz + bz)));
        float r = 1.f / (1.f + expf(-(xr + br)));
        float hh = tanhf(xh + r * bh);
        h = (1.f - z) * hh;
    }
    g_h1[idx] = h;
}

// ---------------- kernel: out[bt][e] = c[e] ---------------------------------
__global__ void k_init_out(float* __restrict__ out) {
    int idx = blockIdx.x * 256 + threadIdx.x;
    if (idx < BT * E_) out[idx] = g_c[idx % E_];
}

// ---------------- kernel: out += h1 @ M (split-K, atomics) ------------------
// BM=64 (bt), BN=128 (e pad), BK=32, splits=8 over K=1000
__global__ __launch_bounds__(256) void k_gemm_out(float* __restrict__ out) {
    __shared__ __align__(16) float As[32][72];
    __shared__ __align__(16) float Bs[32][128];
    const int t = threadIdx.x;
    const int tx = t & 31, ty = t >> 5;
    const int m0 = blockIdx.x * 64;
    const int kbeg = blockIdx.y * 125;
    const int kend = kbeg + 125;

    ull acc[8][2];
#pragma unroll
    for (int i = 0; i < 8; i++) { acc[i][0] = 0ull; acc[i][1] = 0ull; }

    for (int k0 = kbeg; k0 < kend; k0 += 32) {
#pragma unroll
        for (int r = 0; r < 8; r++) {
            int m = ty * 8 + r;
            int k = k0 + tx;
            As[tx][m] = (k < kend) ? g_h1[(size_t)(m0 + m) * U_ + k] : 0.f;
        }
#pragma unroll
        for (int i = 0; i < 16; i++) {
            int idx = t + i * 256;
            int kk = idx >> 7, e = idx & 127;
            int v = k0 + kk;
            Bs[kk][e] = (e < E_ && v < kend) ? g_M[v * E_ + e] : 0.f;
        }
        __syncthreads();
#pragma unroll
        for (int kk = 0; kk < 32; kk++) {
            float4 b4 = *(const float4*)&Bs[kk][tx * 4];
            ull b01 = f2pack(b4.x, b4.y);
            ull b23 = f2pack(b4.z, b4.w);
            float4 av0 = *(const float4*)&As[kk][ty * 8];
            float4 av1 = *(const float4*)&As[kk][ty * 8 + 4];
            float av[8] = {av0.x, av0.y, av0.z, av0.w, av1.x, av1.y, av1.z, av1.w};
#pragma unroll
            for (int i = 0; i < 8; i++) {
                ull aa = f2pack(av[i], av[i]);
                acc[i][0] = ffma2(aa, b01, acc[i][0]);
                acc[i][1] = ffma2(aa, b23, acc[i][1]);
            }
        }
        __syncthreads();
    }

    if (tx < 25) {
#pragma unroll
        for (int i = 0; i < 8; i++) {
            int m = m0 + ty * 8 + i;       // < 1600 always
            float e0, e1, e2, e3;
            f2unpack(acc[i][0], e0, e1);
            f2unpack(acc[i][1], e2, e3);
            float* p = &out[m * E_ + tx * 4];
            atomicAdd(p + 0, e0); atomicAdd(p + 1, e1);
            atomicAdd(p + 2, e2); atomicAdd(p + 3, e3);
        }
    }
}

// ---------------- launch ----------------------------------------------------
extern "C" void kernel_launch(void* const* d_in, const int* in_sizes, int n_in,
                              void* d_out, int out_size) {
    (void)in_sizes; (void)n_in; (void)out_size;
    const int*   target     = (const int*)d_in[1];
    const int*   start_tok  = (const int*)d_in[2];
    const float* emb        = (const float*)d_in[3];
    const float* dec_kernel = (const float*)d_in[7];
    const float* dec_bias   = (const float*)d_in[9];
    const float* fc_w       = (const float*)d_in[10];
    const float* fc_b       = (const float*)d_in[11];
    float*       out        = (float*)d_out;

    k_zero<<<392, 256>>>();
    k_c<<<64, 128>>>(fc_b, emb);
    k_gather<<<BT, 128>>>(target, start_tok, emb);
    k_gemm_M<<<dim3(16, 32), 256>>>(fc_w, emb);
    k_gemm_gx<<<dim3(24, 25), 256>>>(dec_kernel, dec_bias);
    k_h1<<<(BT * U_ + 255) / 256, 256>>>(dec_bias);
    k_init_out<<<(BT * E_ + 255) / 256, 256>>>(out);
    k_gemm_out<<<dim3(25, 8), 256>>>(out);
}

// round 2
// speedup vs baseline: 1.6899x; 1.6899x over previous
#include <cuda_runtime.h>
#include <math.h>

// Problem constants
#define B_  64
#define T_  25
#define BT  1600        // B*T
#define E_  100
#define U_  1000
#define V_  32001
#define G3  3000        // 3*U

typedef unsigned long long ull;

// ---------------- scratch (device globals; no allocation allowed) ----------
__device__ float g_M[U_ * E_];      // fc_w @ emb_table   [1000,100]
__device__ float g_c[128];          // fc_b @ emb_table   [100]
__device__ float g_embd[BT * E_];   // gathered decoder-input embeddings
__device__ int   g_tok[BT];         // tokens (for mask)
__device__ float g_gx[BT * G3];     // emb_d @ dec_kernel + dec_bias[0]
__device__ float g_h1[BT * U_];     // GRU output (masked)

// ---------------- packed f32x2 helpers -------------------------------------
__device__ __forceinline__ ull f2pack(float lo, float hi) {
    ull r; asm("mov.b64 %0, {%1, %2};" : "=l"(r) : "f"(lo), "f"(hi)); return r;
}
__device__ __forceinline__ void f2unpack(ull v, float& lo, float& hi) {
    asm("mov.b64 {%0, %1}, %2;" : "=f"(lo), "=f"(hi) : "l"(v));
}
__device__ __forceinline__ ull ffma2(ull a, ull b, ull c) {
    ull d; asm("fma.rn.f32x2 %0, %1, %2, %3;" : "=l"(d) : "l"(a), "l"(b), "l"(c)); return d;
}

// ---------------- tf32 mma helpers ------------------------------------------
__device__ __forceinline__ unsigned tf32cvt(float f) {
    unsigned u; asm("cvt.rna.tf32.f32 %0, %1;" : "=r"(u) : "f"(f)); return u;
}
__device__ __forceinline__ void mma_tf32(float c[4], unsigned a0, unsigned a1,
                                         unsigned a2, unsigned a3,
                                         unsigned b0, unsigned b1) {
    asm volatile(
        "mma.sync.aligned.m16n8k8.row.col.f32.tf32.tf32.f32 "
        "{%0,%1,%2,%3}, {%4,%5,%6,%7}, {%8,%9}, {%0,%1,%2,%3};"
        : "+f"(c[0]), "+f"(c[1]), "+f"(c[2]), "+f"(c[3])
        : "r"(a0), "r"(a1), "r"(a2), "r"(a3), "r"(b0), "r"(b1));
}

// ---------------- cp.async helpers ------------------------------------------
__device__ __forceinline__ unsigned smem_u32(const void* p) {
    return (unsigned)__cvta_generic_to_shared(p);
}
__device__ __forceinline__ void cpa4(unsigned d, const void* s, int sz) {
    asm volatile("cp.async.ca.shared.global [%0], [%1], 4, %2;"
                 :: "r"(d), "l"(s), "r"(sz));
}
__device__ __forceinline__ void cpa16(unsigned d, const void* s, int sz) {
    asm volatile("cp.async.ca.shared.global [%0], [%1], 16, %2;"
                 :: "r"(d), "l"(s), "r"(sz));
}

// ---------------- kernel: zero M and c --------------------------------------
__global__ void k_zero() {
    int i = blockIdx.x * 256 + threadIdx.x;
    if (i < U_ * E_)              g_M[i] = 0.f;
    else if (i < U_ * E_ + 128)   g_c[i - U_ * E_] = 0.f;
}

// ---------------- kernel: c = fc_b @ emb_table ------------------------------
__global__ __launch_bounds__(128) void k_c(const float* __restrict__ fcb,
                                           const float* __restrict__ emb) {
    __shared__ float s[4][100];
    const int w = threadIdx.x >> 5, l = threadIdx.x & 31;
    const int chunk = 501;
    const int v0 = blockIdx.x * chunk;
    const int v1 = min(v0 + chunk, V_);
    float a0 = 0.f, a1 = 0.f, a2 = 0.f, a3 = 0.f;
    if (l < 25) {
        for (int v = v0 + w; v < v1; v += 4) {
            float fb = fcb[v];
            float4 e4 = *(const float4*)(emb + (size_t)v * E_ + l * 4);
            a0 = fmaf(fb, e4.x, a0); a1 = fmaf(fb, e4.y, a1);
            a2 = fmaf(fb, e4.z, a2); a3 = fmaf(fb, e4.w, a3);
        }
        s[w][l * 4 + 0] = a0; s[w][l * 4 + 1] = a1;
        s[w][l * 4 + 2] = a2; s[w][l * 4 + 3] = a3;
    }
    __syncthreads();
    int t = threadIdx.x;
    if (t < 100) {
        float sum = s[0][t] + s[1][t] + s[2][t] + s[3][t];
        atomicAdd(&g_c[t], sum);
    }
}

// ---------------- kernel: gather decoder input embeddings -------------------
__global__ __launch_bounds__(128) void k_gather(const int* __restrict__ target,
                                                const int* __restrict__ start_tok,
                                                const float* __restrict__ emb) {
    const int bt = blockIdx.x;
    const int b = bt / T_, t = bt % T_;
    const int tok = (t == 0) ? start_tok[0] : target[b * T_ + t - 1];
    if (threadIdx.x == 0) g_tok[bt] = tok;
    for (int e = threadIdx.x; e < E_; e += blockDim.x)
        g_embd[bt * E_ + e] = emb[(size_t)tok * E_ + e];
}

// ---------------- kernel: M += fc_w @ emb  (tf32 tensor-core, split-K) ------
// BM=64 (u), BN=112 (e pad; 100 valid), BK=32, 8 warps = 4(m)x2(n),
// warp tile 16x56 = 7 mma n-tiles. Double-buffered cp.async. 32 K-splits.
#define MSPLIT 32
#define MSPLEN 1001     // ceil(32001/32)
__global__ __launch_bounds__(256) void k_gemm_M_tc(const float* __restrict__ fcw,
                                                   const float* __restrict__ emb) {
    __shared__ __align__(16) float As[2][64][36];   // [k-pad 36] m-major
    __shared__ __align__(16) float Bs[2][32][120];  // [n-pad 120] k-major
    const int t    = threadIdx.x;
    const int lane = t & 31;
    const int wid  = t >> 5;
    const int warp_m = wid & 3;       // 0..3  -> m offset 16*warp_m
    const int warp_n = wid >> 2;      // 0..1  -> n offset 56*warp_n
    const int u0   = blockIdx.x * 64;
    const int kbeg = blockIdx.y * MSPLEN;
    const int kend = min(kbeg + MSPLEN, V_);

    // zero the B pad columns (100..119) in both buffers, once
    for (int i = t; i < 2 * 32 * 20; i += 256) {
        int buf = i / (32 * 20);
        int r   = (i / 20) % 32;
        Bs[buf][r][100 + (i % 20)] = 0.f;
    }

    // ---- stage: issue async copies for K-chunk [k0, k0+32) into buffer b
    auto stage = [&](int b, int k0) {
        int kg = k0 + (t & 31);
        bool kval = kg < kend;
        const int mbase = t >> 5;
#pragma unroll
        for (int r = 0; r < 8; r++) {
            int m = mbase + r * 8;
            int u = u0 + m;
            const float* src = fcw + (size_t)u * V_ + kg;
            int sz = (kval && u < U_) ? 4 : 0;
            cpa4(smem_u32(&As[b][m][t & 31]), src, sz);
        }
        for (int idx = t; idx < 800; idx += 256) {       // 32 rows x 25 float4
            int r = idx / 25, c4 = idx % 25;
            int v = k0 + r;
            const float* src = emb + (size_t)v * E_ + c4 * 4;
            int sz = (v < kend) ? 16 : 0;
            cpa16(smem_u32(&Bs[b][r][c4 * 4]), src, sz);
        }
        asm volatile("cp.async.commit_group;");
    };

    float acc[7][4];
#pragma unroll
    for (int i = 0; i < 7; i++)
#pragma unroll
        for (int j = 0; j < 4; j++) acc[i][j] = 0.f;

    stage(0, kbeg);

    const int row = lane >> 2;        // 0..7
    const int col = lane & 3;         // 0..3
    int b = 0;
    for (int k0 = kbeg; k0 < kend; k0 += 32) {
        if (k0 + 32 < kend) {
            stage(b ^ 1, k0 + 32);
            asm volatile("cp.async.wait_group 1;");
        } else {
            asm volatile("cp.async.wait_group 0;");
        }
        __syncthreads();

#pragma unroll
        for (int ks = 0; ks < 4; ks++) {
            const int kk = ks * 8;
            unsigned A0 = tf32cvt(As[b][warp_m * 16 + row][kk + col]);
            unsigned A1 = tf32cvt(As[b][warp_m * 16 + row + 8][kk + col]);
            unsigned A2 = tf32cvt(As[b][warp_m * 16 + row][kk + col + 4]);
            unsigned A3 = tf32cvt(As[b][warp_m * 16 + row + 8][kk + col + 4]);
#pragma unroll
            for (int nt = 0; nt < 7; nt++) {
                int n0 = warp_n * 56 + nt * 8;
                unsigned B0 = tf32cvt(Bs[b][kk + col][n0 + row]);
                unsigned B1 = tf32cvt(Bs[b][kk + col + 4][n0 + row]);
                mma_tf32(acc[nt], A0, A1, A2, A3, B0, B1);
            }
        }
        __syncthreads();   // before restaging this buffer
        b ^= 1;
    }

    // epilogue: atomicAdd into g_M
    const int r0 = u0 + warp_m * 16 + row;
#pragma unroll
    for (int nt = 0; nt < 7; nt++) {
        int n = warp_n * 56 + nt * 8 + col * 2;
        if (n < E_) {
            if (r0 < U_) {
                atomicAdd(&g_M[r0 * E_ + n], acc[nt][0]);
                if (n + 1 < E_) atomicAdd(&g_M[r0 * E_ + n + 1], acc[nt][1]);
            }
            if (r0 + 8 < U_) {
                atomicAdd(&g_M[(r0 + 8) * E_ + n], acc[nt][2]);
                if (n + 1 < E_) atomicAdd(&g_M[(r0 + 8) * E_ + n + 1], acc[nt][3]);
            }
        }
    }
}

// ---------------- kernel: gx = emb_d @ dec_kernel + dec_bias[0] -------------
__global__ __launch_bounds__(256) void k_gemm_gx(const float* __restrict__ W,
                                                 const float* __restrict__ bias) {
    __shared__ __align__(16) float As[25][72];
    __shared__ __align__(16) float Bs[25][128];
    const int t = threadIdx.x;
    const int tx = t & 31, ty = t >> 5;
    const int j0 = blockIdx.x * 128;
    const int m0 = blockIdx.y * 64;

    ull acc[8][2];
#pragma unroll
    for (int i = 0; i < 8; i++) { acc[i][0] = 0ull; acc[i][1] = 0ull; }

    for (int k0 = 0; k0 < E_; k0 += 25) {
        for (int idx = t; idx < 64 * 25; idx += 256) {
            int m = idx / 25, k = idx % 25;
            As[k][m] = g_embd[(m0 + m) * E_ + k0 + k];
        }
        for (int idx = t; idx < 25 * 128; idx += 256) {
            int k = idx >> 7, j = idx & 127;
            int jj = j0 + j;
            Bs[k][j] = (jj < G3) ? W[(size_t)(k0 + k) * G3 + jj] : 0.f;
        }
        __syncthreads();
#pragma unroll
        for (int kk = 0; kk < 25; kk++) {
            float4 b4 = *(const float4*)&Bs[kk][tx * 4];
            ull b01 = f2pack(b4.x, b4.y);
            ull b23 = f2pack(b4.z, b4.w);
            float4 av0 = *(const float4*)&As[kk][ty * 8];
            float4 av1 = *(const float4*)&As[kk][ty * 8 + 4];
            float av[8] = {av0.x, av0.y, av0.z, av0.w, av1.x, av1.y, av1.z, av1.w};
#pragma unroll
            for (int i = 0; i < 8; i++) {
                ull aa = f2pack(av[i], av[i]);
                acc[i][0] = ffma2(aa, b01, acc[i][0]);
                acc[i][1] = ffma2(aa, b23, acc[i][1]);
            }
        }
        __syncthreads();
    }

    const int j = j0 + tx * 4;
#pragma unroll
    for (int i = 0; i < 8; i++) {
        int m = m0 + ty * 8 + i;
        float e0, e1, e2, e3;
        f2unpack(acc[i][0], e0, e1);
        f2unpack(acc[i][1], e2, e3);
        float* p = &g_gx[(size_t)m * G3 + j];
        if (j + 0 < G3) p[0] = e0 + bias[j + 0];
        if (j + 1 < G3) p[1] = e1 + bias[j + 1];
        if (j + 2 < G3) p[2] = e2 + bias[j + 2];
        if (j + 3 < G3) p[3] = e3 + bias[j + 3];
    }
}

// ---------------- kernel: GRU nonlinearity + mask ---------------------------
__global__ void k_h1(const float* __restrict__ dec_bias) {
    int idx = blockIdx.x * 256 + threadIdx.x;
    if (idx >= BT * U_) return;
    int bt = idx / U_, u = idx - bt * U_;
    float h;
    if (g_tok[bt] == 0) {
        h = 0.f;
    } else {
        float xz = g_gx[(size_t)bt * G3 + u];
        float xr = g_gx[(size_t)bt * G3 + 1000 + u];
        float xh = g_gx[(size_t)bt * G3 + 2000 + u];
        float bz = dec_bias[3000 + u];
        float br = dec_bias[4000 + u];
        float bh = dec_bias[5000 + u];
        float z = 1.f / (1.f + expf(-(xz + bz)));
        float r = 1.f / (1.f + expf(-(xr + br)));
        float hh = tanhf(xh + r * bh);
        h = (1.f - z) * hh;
    }
    g_h1[idx] = h;
}

// ---------------- kernel: out[bt][e] = c[e] ---------------------------------
__global__ void k_init_out(float* __restrict__ out) {
    int idx = blockIdx.x * 256 + threadIdx.x;
    if (idx < BT * E_) out[idx] = g_c[idx % E_];
}

// ---------------- kernel: out += h1 @ M (split-K, atomics) ------------------
__global__ __launch_bounds__(256) void k_gemm_out(float* __restrict__ out) {
    __shared__ __align__(16) float As[32][72];
    __shared__ __align__(16) float Bs[32][128];
    const int t = threadIdx.x;
    const int tx = t & 31, ty = t >> 5;
    const int m0 = blockIdx.x * 64;
    const int kbeg = blockIdx.y * 125;
    const int kend = kbeg + 125;

    ull acc[8][2];
#pragma unroll
    for (int i = 0; i < 8; i++) { acc[i][0] = 0ull; acc[i][1] = 0ull; }

    for (int k0 = kbeg; k0 < kend; k0 += 32) {
#pragma unroll
        for (int r = 0; r < 8; r++) {
            int m = ty * 8 + r;
            int k = k0 + tx;
            As[tx][m] = (k < kend) ? g_h1[(size_t)(m0 + m) * U_ + k] : 0.f;
        }
#pragma unroll
        for (int i = 0; i < 16; i++) {
            int idx = t + i * 256;
            int kk = idx >> 7, e = idx & 127;
            int v = k0 + kk;
            Bs[kk][e] = (e < E_ && v < kend) ? g_M[v * E_ + e] : 0.f;
        }
        __syncthreads();
#pragma unroll
        for (int kk = 0; kk < 32; kk++) {
            float4 b4 = *(const float4*)&Bs[kk][tx * 4];
            ull b01 = f2pack(b4.x, b4.y);
            ull b23 = f2pack(b4.z, b4.w);
            float4 av0 = *(const float4*)&As[kk][ty * 8];
            float4 av1 = *(const float4*)&As[kk][ty * 8 + 4];
            float av[8] = {av0.x, av0.y, av0.z, av0.w, av1.x, av1.y, av1.z, av1.w};
#pragma unroll
            for (int i = 0; i < 8; i++) {
                ull aa = f2pack(av[i], av[i]);
                acc[i][0] = ffma2(aa, b01, acc[i][0]);
                acc[i][1] = ffma2(aa, b23, acc[i][1]);
            }
        }
        __syncthreads();
    }

    if (tx < 25) {
#pragma unroll
        for (int i = 0; i < 8; i++) {
            int m = m0 + ty * 8 + i;
            float e0, e1, e2, e3;
            f2unpack(acc[i][0], e0, e1);
            f2unpack(acc[i][1], e2, e3);
            float* p = &out[m * E_ + tx * 4];
            atomicAdd(p + 0, e0); atomicAdd(p + 1, e1);
            atomicAdd(p + 2, e2); atomicAdd(p + 3, e3);
        }
    }
}

// ---------------- launch ----------------------------------------------------
extern "C" void kernel_launch(void* const* d_in, const int* in_sizes, int n_in,
                              void* d_out, int out_size) {
    (void)in_sizes; (void)n_in; (void)out_size;
    const int*   target     = (const int*)d_in[1];
    const int*   start_tok  = (const int*)d_in[2];
    const float* emb        = (const float*)d_in[3];
    const float* dec_kernel = (const float*)d_in[7];
    const float* dec_bias   = (const float*)d_in[9];
    const float* fc_w       = (const float*)d_in[10];
    const float* fc_b       = (const float*)d_in[11];
    float*       out        = (float*)d_out;

    k_zero<<<392, 256>>>();
    k_c<<<64, 128>>>(fc_b, emb);
    k_gather<<<BT, 128>>>(target, start_tok, emb);
    k_gemm_M_tc<<<dim3(16, MSPLIT), 256>>>(fc_w, emb);
    k_gemm_gx<<<dim3(24, 25), 256>>>(dec_kernel, dec_bias);
    k_h1<<<(BT * U_ + 255) / 256, 256>>>(dec_bias);
    k_init_out<<<(BT * E_ + 255) / 256, 256>>>(out);
    k_gemm_out<<<dim3(25, 8), 256>>>(out);
}

// round 3
// speedup vs baseline: 1.7184x; 1.0168x over previous
#include <cuda_runtime.h>
#include <math.h>

// Problem constants
#define B_  64
#define T_  25
#define BT  1600        // B*T
#define E_  100
#define U_  1000
#define V_  32001
#define G3  3000        // 3*U
#define TOT_A 32001000LL   // U_*V_

typedef unsigned long long ull;

// ---------------- scratch ----------------------------------------------------
__device__ float g_M[U_ * E_];      // fc_w @ emb_table   [1000,100]
__device__ float g_c[128];          // fc_b @ emb_table   [100]
__device__ float g_embd[BT * E_];   // gathered decoder-input embeddings
__device__ int   g_tok[BT];         // tokens (for mask)
__device__ float g_gx[BT * G3];     // emb_d @ dec_kernel + dec_bias[0]
__device__ float g_h1[BT * U_];     // GRU output (masked)

// ---------------- packed f32x2 helpers ---------------------------------------
__device__ __forceinline__ ull f2pack(float lo, float hi) {
    ull r; asm("mov.b64 %0, {%1, %2};" : "=l"(r) : "f"(lo), "f"(hi)); return r;
}
__device__ __forceinline__ void f2unpack(ull v, float& lo, float& hi) {
    asm("mov.b64 {%0, %1}, %2;" : "=f"(lo), "=f"(hi) : "l"(v));
}
__device__ __forceinline__ ull ffma2(ull a, ull b, ull c) {
    ull d; asm("fma.rn.f32x2 %0, %1, %2, %3;" : "=l"(d) : "l"(a), "l"(b), "l"(c)); return d;
}

// ---------------- tf32 mma helpers -------------------------------------------
__device__ __forceinline__ unsigned tf32cvt(float f) {
    unsigned u; asm("cvt.rna.tf32.f32 %0, %1;" : "=r"(u) : "f"(f)); return u;
}
__device__ __forceinline__ void mma_tf32(float c[4], unsigned a0, unsigned a1,
                                         unsigned a2, unsigned a3,
                                         unsigned b0, unsigned b1) {
    asm volatile(
        "mma.sync.aligned.m16n8k8.row.col.f32.tf32.tf32.f32 "
        "{%0,%1,%2,%3}, {%4,%5,%6,%7}, {%8,%9}, {%0,%1,%2,%3};"
        : "+f"(c[0]), "+f"(c[1]), "+f"(c[2]), "+f"(c[3])
        : "r"(a0), "r"(a1), "r"(a2), "r"(a3), "r"(b0), "r"(b1));
}

// ---------------- kernel: zero M and c ---------------------------------------
__global__ void k_zero() {
    int i = blockIdx.x * 256 + threadIdx.x;
    if (i < U_ * E_)              g_M[i] = 0.f;
    else if (i < U_ * E_ + 128)   g_c[i - U_ * E_] = 0.f;
}

// ---------------- kernel: c = fc_b @ emb_table -------------------------------
__global__ __launch_bounds__(128) void k_c(const float* __restrict__ fcb,
                                           const float* __restrict__ emb) {
    __shared__ float s[4][100];
    const int w = threadIdx.x >> 5, l = threadIdx.x & 31;
    const int chunk = 501;
    const int v0 = blockIdx.x * chunk;
    const int v1 = min(v0 + chunk, V_);
    float a0 = 0.f, a1 = 0.f, a2 = 0.f, a3 = 0.f;
    if (l < 25) {
        for (int v = v0 + w; v < v1; v += 4) {
            float fb = fcb[v];
            float4 e4 = *(const float4*)(emb + (size_t)v * E_ + l * 4);
            a0 = fmaf(fb, e4.x, a0); a1 = fmaf(fb, e4.y, a1);
            a2 = fmaf(fb, e4.z, a2); a3 = fmaf(fb, e4.w, a3);
        }
        s[w][l * 4 + 0] = a0; s[w][l * 4 + 1] = a1;
        s[w][l * 4 + 2] = a2; s[w][l * 4 + 3] = a3;
    }
    __syncthreads();
    int t = threadIdx.x;
    if (t < 100) {
        float sum = s[0][t] + s[1][t] + s[2][t] + s[3][t];
        atomicAdd(&g_c[t], sum);
    }
}

// ---------------- kernel: gather decoder input embeddings --------------------
__global__ __launch_bounds__(128) void k_gather(const int* __restrict__ target,
                                                const int* __restrict__ start_tok,
                                                const float* __restrict__ emb) {
    const int bt = blockIdx.x;
    const int b = bt / T_, t = bt % T_;
    const int tok = (t == 0) ? start_tok[0] : target[b * T_ + t - 1];
    if (threadIdx.x == 0) g_tok[bt] = tok;
    for (int e = threadIdx.x; e < E_; e += blockDim.x)
        g_embd[bt * E_ + e] = emb[(size_t)tok * E_ + e];
}

// ---------------- kernel: M += fc_w @ emb (tf32, stage-time cvt) -------------
// BM=64 (u), BN=112 (e; 100 valid), BK=32. 8 warps = 4(m)x2(n), warp 16x56.
// A staged into shifted natural layout (aligned LDG.128 despite V=32001 rows),
// B staged into fragment-major layout (in-loop LDS.128 only). 36 K-splits.
#define MK_SPL 36
#define MK_LEN 896      // 36*896 = 32256 >= 32001; 896 % 32 == 0
#define MK_CH  28       // 896/32
__global__ __launch_bounds__(256, 2) void k_gemm_M_tc(const float* __restrict__ fcw,
                                                      const float* __restrict__ emb) {
    __shared__ unsigned As[2][64][40];          // shifted: As[m][s] = k (s - r_m)
    __shared__ unsigned Bf[2][2][4][32][20];    // [buf][wn][ks][lane][idx pad20]
    const int t = threadIdx.x;
    const int lane = t & 31, wid = t >> 5;
    const int wm = wid & 3, wn = wid >> 2;
    const int row = lane >> 2, col = lane & 3;
    const int u0 = blockIdx.x * 64;
    const int kbeg = blockIdx.y * MK_LEN;

    // ---- A unit descriptors: 576 units = 64 rows x 9 float4-windows
    long long aBase[3]; int aOff[3], aD[3]; bool aUse[3];
#pragma unroll
    for (int q = 0; q < 3; q++) {
        int i = t + 256 * q;
        bool use = (i < 576);
        int m = use ? i / 9 : 0, j = use ? i % 9 : 0;
        int u = u0 + m, r = u & 3;
        aUse[q] = use;
        aBase[q] = (u < U_) ? ((long long)u * V_ + kbeg - r + 4 * j) : -(1LL << 40);
        aOff[q] = m * 40 + 4 * j;
        aD[q]   = 4 * j - r;
    }

    // ---- B unit descriptors: 896 units = 32 v-rows x 28 float4s (112 n)
    const float* bPtr[4]; int bOff[4], bVl[4]; bool bUse[4];
#pragma unroll
    for (int q = 0; q < 4; q++) {
        int i = t + 256 * q;
        int vl = (i < 896) ? i / 28 : 0, n4 = (i < 896) ? i % 28 : 0;
        int n = n4 * 4;
        bUse[q] = (i < 896) && (n4 < 25);
        bVl[q] = vl;
        bPtr[q] = emb + (size_t)(kbeg + vl) * E_ + n;
        int k7 = vl & 7, reg = k7 >> 2, colB = k7 & 3, ks = vl >> 3;
        int wnn = (n >= 56) ? 1 : 0;
        int rem = n - 56 * wnn;
        int nt = rem >> 3, rw = rem & 7;
        int off = ((wnn * 4 + ks) * 32 + (rw * 4 + colB)) * 20 + (nt * 2 + reg);
        bOff[q] = off;
        if ((i < 896) && n4 >= 25) {  // pad region: write zeros once, both bufs
            unsigned* B0 = &Bf[0][0][0][0][0];
            unsigned* B1 = &Bf[1][0][0][0][0];
#pragma unroll
            for (int e = 0; e < 4; e++) { B0[off + 80 * e] = 0u; B1[off + 80 * e] = 0u; }
        }
    }

    float4 aReg[3], bReg[4];
    auto ldc = [&](int c) {
        long long off = 32LL * c;
#pragma unroll
        for (int q = 0; q < 3; q++) {
            bool ok = aUse[q] && (aBase[q] >= 0) && (aBase[q] + off + 3 < TOT_A);
            aReg[q] = ok ? *(const float4*)(fcw + aBase[q] + off)
                         : make_float4(0.f, 0.f, 0.f, 0.f);
        }
        int vadd = 32 * c;
#pragma unroll
        for (int q = 0; q < 4; q++) {
            bool ok = bUse[q] && (kbeg + vadd + bVl[q] < V_);
            bReg[q] = ok ? *(const float4*)(bPtr[q] + vadd * E_)
                         : make_float4(0.f, 0.f, 0.f, 0.f);
        }
    };
    auto stc = [&](int c, int b) {
        int kg = kbeg + 32 * c;
        bool fast = (kg + 36 <= V_);
        unsigned* Ab = &As[b][0][0];
#pragma unroll
        for (int q = 0; q < 3; q++) if (aUse[q]) {
            float4 v = aReg[q];
            if (!fast) {
                if (kg + aD[q] + 0 >= V_) v.x = 0.f;
                if (kg + aD[q] + 1 >= V_) v.y = 0.f;
                if (kg + aD[q] + 2 >= V_) v.z = 0.f;
                if (kg + aD[q] + 3 >= V_) v.w = 0.f;
            }
            uint4 u4;
            u4.x = tf32cvt(v.x); u4.y = tf32cvt(v.y);
            u4.z = tf32cvt(v.z); u4.w = tf32cvt(v.w);
            *(uint4*)(Ab + aOff[q]) = u4;
        }
        unsigned* Bb = &Bf[b][0][0][0][0];
#pragma unroll
        for (int q = 0; q < 4; q++) if (bUse[q]) {
            float4 v = bReg[q];
            Bb[bOff[q] +   0] = tf32cvt(v.x);
            Bb[bOff[q] +  80] = tf32cvt(v.y);
            Bb[bOff[q] + 160] = tf32cvt(v.z);
            Bb[bOff[q] + 240] = tf32cvt(v.w);
        }
    };

    float acc[7][4];
#pragma unroll
    for (int i = 0; i < 7; i++)
#pragma unroll
        for (int j = 0; j < 4; j++) acc[i][j] = 0.f;

    const int r1  = row & 3;              // (u0 + wm*16 + row) & 3, u0%4==0
    const int moA = (wm * 16 + row) * 40;

    auto domma = [&](int b) {
        const unsigned* Ab = &As[b][0][0];
#pragma unroll
        for (int ks = 0; ks < 4; ks++) {
            int kk = ks * 8;
            unsigned A0 = Ab[moA +       kk + col + r1];
            unsigned A1 = Ab[moA + 320 + kk + col + r1];
            unsigned A2 = Ab[moA +       kk + col + 4 + r1];
            unsigned A3 = Ab[moA + 320 + kk + col + 4 + r1];
            const unsigned* Bp = &Bf[b][wn][ks][lane][0];
            uint4 b0 = *(const uint4*)(Bp);
            uint4 b1 = *(const uint4*)(Bp + 4);
            uint4 b2 = *(const uint4*)(Bp + 8);
            uint4 b3 = *(const uint4*)(Bp + 12);
            unsigned bb[16] = {b0.x, b0.y, b0.z, b0.w, b1.x, b1.y, b1.z, b1.w,
                               b2.x, b2.y, b2.z, b2.w, b3.x, b3.y, b3.z, b3.w};
#pragma unroll
            for (int nt = 0; nt < 7; nt++)
                mma_tf32(acc[nt], A0, A1, A2, A3, bb[nt * 2], bb[nt * 2 + 1]);
        }
    };

    ldc(0);
    stc(0, 0);
    __syncthreads();
#pragma unroll 1
    for (int c = 0; c < MK_CH; c++) {
        int b = c & 1;
        if (c + 1 < MK_CH) ldc(c + 1);
        domma(b);
        if (c + 1 < MK_CH) stc(c + 1, b ^ 1);
        __syncthreads();
    }

    const int r0 = u0 + wm * 16 + row;
#pragma unroll
    for (int nt = 0; nt < 7; nt++) {
        int n = wn * 56 + nt * 8 + col * 2;
        if (n < E_) {
            if (r0 < U_) {
                atomicAdd(&g_M[r0 * E_ + n],     acc[nt][0]);
                atomicAdd(&g_M[r0 * E_ + n + 1], acc[nt][1]);
            }
            if (r0 + 8 < U_) {
                atomicAdd(&g_M[(r0 + 8) * E_ + n],     acc[nt][2]);
                atomicAdd(&g_M[(r0 + 8) * E_ + n + 1], acc[nt][3]);
            }
        }
    }
}

// ---------------- kernel: gx = emb_d @ dec_kernel + dec_bias[0] (tf32) ------
// BM=64 (bt), BN=128 (j), K=100 padded to 104, single shot.
__global__ __launch_bounds__(256) void k_gemm_gx_tc(const float* __restrict__ W,
                                                    const float* __restrict__ bias) {
    __shared__ float As[64][108];
    __shared__ float Bs[104][136];
    const int t = threadIdx.x;
    const int lane = t & 31, wid = t >> 5;
    const int wm = wid & 3, wn = wid >> 2;
    const int row = lane >> 2, col = lane & 3;
    const int m0 = blockIdx.y * 64;
    const int j0 = blockIdx.x * 128;

    for (int i = t; i < 64 * 26; i += 256) {
        int m = i / 26, c = (i % 26) * 4;
        float4 v = make_float4(0.f, 0.f, 0.f, 0.f);
        if (c < 100) v = *(const float4*)(g_embd + (size_t)(m0 + m) * E_ + c);
        *(float4*)&As[m][c] = v;
    }
    for (int i = t; i < 104 * 32; i += 256) {
        int k = i / 32, c4 = i % 32;
        int j = j0 + c4 * 4;
        float4 v = make_float4(0.f, 0.f, 0.f, 0.f);
        if (k < 100) {
            if (j + 3 < G3) v = *(const float4*)(W + (size_t)k * G3 + j);
            else {
                if (j     < G3) v.x = W[(size_t)k * G3 + j];
                if (j + 1 < G3) v.y = W[(size_t)k * G3 + j + 1];
                if (j + 2 < G3) v.z = W[(size_t)k * G3 + j + 2];
            }
        }
        *(float4*)&Bs[k][c4 * 4] = v;
    }
    __syncthreads();

    float acc[8][4];
#pragma unroll
    for (int i = 0; i < 8; i++)
#pragma unroll
        for (int j = 0; j < 4; j++) acc[i][j] = 0.f;

#pragma unroll
    for (int ks = 0; ks < 13; ks++) {
        int kk = ks * 8;
        unsigned A0 = tf32cvt(As[wm * 16 + row][kk + col]);
        unsigned A1 = tf32cvt(As[wm * 16 + row + 8][kk + col]);
        unsigned A2 = tf32cvt(As[wm * 16 + row][kk + col + 4]);
        unsigned A3 = tf32cvt(As[wm * 16 + row + 8][kk + col + 4]);
#pragma unroll
        for (int nt = 0; nt < 8; nt++) {
            int n0 = wn * 64 + nt * 8;
            unsigned B0 = tf32cvt(Bs[kk + col][n0 + row]);
            unsigned B1 = tf32cvt(Bs[kk + col + 4][n0 + row]);
            mma_tf32(acc[nt], A0, A1, A2, A3, B0, B1);
        }
    }

    const int m1 = m0 + wm * 16 + row;
#pragma unroll
    for (int nt = 0; nt < 8; nt++) {
        int j = j0 + wn * 64 + nt * 8 + col * 2;
        if (j < G3) {
            float2 bb = *(const float2*)(bias + j);
            float2 o1 = make_float2(acc[nt][0] + bb.x, acc[nt][1] + bb.y);
            float2 o2 = make_float2(acc[nt][2] + bb.x, acc[nt][3] + bb.y);
            *(float2*)(g_gx + (size_t)m1 * G3 + j) = o1;
            *(float2*)(g_gx + (size_t)(m1 + 8) * G3 + j) = o2;
        }
    }
}

// ---------------- kernel: GRU nonlinearity + mask ----------------------------
__global__ void k_h1(const float* __restrict__ dec_bias) {
    int idx = blockIdx.x * 256 + threadIdx.x;
    if (idx >= BT * U_) return;
    int bt = idx / U_, u = idx - bt * U_;
    float h;
    if (g_tok[bt] == 0) {
        h = 0.f;
    } else {
        float xz = g_gx[(size_t)bt * G3 + u];
        float xr = g_gx[(size_t)bt * G3 + 1000 + u];
        float xh = g_gx[(size_t)bt * G3 + 2000 + u];
        float bz = dec_bias[3000 + u];
        float br = dec_bias[4000 + u];
        float bh = dec_bias[5000 + u];
        float z = 1.f / (1.f + expf(-(xz + bz)));
        float r = 1.f / (1.f + expf(-(xr + br)));
        float hh = tanhf(xh + r * bh);
        h = (1.f - z) * hh;
    }
    g_h1[idx] = h;
}

// ---------------- kernel: out[bt][e] = c[e] ----------------------------------
__global__ void k_init_out(float* __restrict__ out) {
    int idx = blockIdx.x * 256 + threadIdx.x;
    if (idx < BT * E_) out[idx] = g_c[idx % E_];
}

// ---------------- kernel: out += h1 @ M (split-K, atomics, f32x2) ------------
__global__ __launch_bounds__(256) void k_gemm_out(float* __restrict__ out) {
    __shared__ __align__(16) float As[32][72];
    __shared__ __align__(16) float Bs[32][128];
    const int t = threadIdx.x;
    const int tx = t & 31, ty = t >> 5;
    const int m0 = blockIdx.x * 64;
    const int kbeg = blockIdx.y * 125;
    const int kend = kbeg + 125;

    ull acc[8][2];
#pragma unroll
    for (int i = 0; i < 8; i++) { acc[i][0] = 0ull; acc[i][1] = 0ull; }

    for (int k0 = kbeg; k0 < kend; k0 += 32) {
#pragma unroll
        for (int r = 0; r < 8; r++) {
            int m = ty * 8 + r;
            int k = k0 + tx;
            As[tx][m] = (k < kend) ? g_h1[(size_t)(m0 + m) * U_ + k] : 0.f;
        }
#pragma unroll
        for (int i = 0; i < 16; i++) {
            int idx = t + i * 256;
            int kk = idx >> 7, e = idx & 127;
            int v = k0 + kk;
            Bs[kk][e] = (e < E_ && v < kend) ? g_M[v * E_ + e] : 0.f;
        }
        __syncthreads();
#pragma unroll
        for (int kk = 0; kk < 32; kk++) {
            float4 b4 = *(const float4*)&Bs[kk][tx * 4];
            ull b01 = f2pack(b4.x, b4.y);
            ull b23 = f2pack(b4.z, b4.w);
            float4 av0 = *(const float4*)&As[kk][ty * 8];
            float4 av1 = *(const float4*)&As[kk][ty * 8 + 4];
            float av[8] = {av0.x, av0.y, av0.z, av0.w, av1.x, av1.y, av1.z, av1.w};
#pragma unroll
            for (int i = 0; i < 8; i++) {
                ull aa = f2pack(av[i], av[i]);
                acc[i][0] = ffma2(aa, b01, acc[i][0]);
                acc[i][1] = ffma2(aa, b23, acc[i][1]);
            }
        }
        __syncthreads();
    }

    if (tx < 25) {
#pragma unroll
        for (int i = 0; i < 8; i++) {
            int m = m0 + ty * 8 + i;
            float e0, e1, e2, e3;
            f2unpack(acc[i][0], e0, e1);
            f2unpack(acc[i][1], e2, e3);
            float* p = &out[m * E_ + tx * 4];
            atomicAdd(p + 0, e0); atomicAdd(p + 1, e1);
            atomicAdd(p + 2, e2); atomicAdd(p + 3, e3);
        }
    }
}

// ---------------- launch -----------------------------------------------------
extern "C" void kernel_launch(void* const* d_in, const int* in_sizes, int n_in,
                              void* d_out, int out_size) {
    (void)in_sizes; (void)n_in; (void)out_size;
    const int*   target     = (const int*)d_in[1];
    const int*   start_tok  = (const int*)d_in[2];
    const float* emb        = (const float*)d_in[3];
    const float* dec_kernel = (const float*)d_in[7];
    const float* dec_bias   = (const float*)d_in[9];
    const float* fc_w       = (const float*)d_in[10];
    const float* fc_b       = (const float*)d_in[11];
    float*       out        = (float*)d_out;

    k_zero<<<392, 256>>>();
    k_c<<<64, 128>>>(fc_b, emb);
    k_gather<<<BT, 128>>>(target, start_tok, emb);
    k_gemm_M_tc<<<dim3(16, MK_SPL), 256>>>(fc_w, emb);
    k_gemm_gx_tc<<<dim3(24, 25), 256>>>(dec_kernel, dec_bias);
    k_h1<<<(BT * U_ + 255) / 256, 256>>>(dec_bias);
    k_init_out<<<(BT * E_ + 255) / 256, 256>>>(out);
    k_gemm_out<<<dim3(25, 8), 256>>>(out);
}